// round 11
// baseline (speedup 1.0000x reference)
#include <cuda_runtime.h>
#include <cstdint>

#define D    100
#define Kn   32
#define NBA  4            // attn nodes per block -> M = 128
#define M    128
#define AW   104          // A row stride (raw h; cols 100..103 = wei,0,0,0)
#define TA   256
#define NMAX 50000
#define NT   13
#define KTB  7            // attn k tiles of 16 (112, zero-padded from 101)
#define KP4  4            // attn k-tile PAIRS (uint4): (0,1)(2,3)(4,5)(6,-)
#define SSW  112
// mlp
#define MN   64
#define SA2  212
#define KT2  25           // 2D = 200 = exactly 25 k-tiles of 8
#define KP2  13           // mlp k-tile pairs: (0,1)...(22,23),(24,-)

__device__ float g_msg[NMAX * D];
__device__ uint4 g_W1f4[NT * KP4 * 32];   // bf16 frags, 2 k-tiles per uint4
__device__ uint4 g_W2f4[NT * KP2 * 32];   // tf32 frags, 2 k-tiles per uint4

__device__ __forceinline__ float tanh_fast(float x) {
    float r; asm("tanh.approx.f32 %0, %1;" : "=f"(r) : "f"(x)); return r;
}
__device__ __forceinline__ uint32_t f2tf32(float x) {
    uint32_t r; asm("cvt.rna.tf32.f32 %0, %1;" : "=r"(r) : "f"(x)); return r;
}
__device__ __forceinline__ uint32_t pack_bf16(float lo, float hi) {
    uint32_t r; asm("cvt.rn.bf16x2.f32 %0, %1, %2;" : "=r"(r) : "f"(hi), "f"(lo)); return r;
}
__device__ __forceinline__ uint32_t smem_u32(const void* p) {
    uint32_t a;
    asm("{ .reg .u64 t; cvta.to.shared.u64 t, %1; cvt.u32.u64 %0, t; }" : "=r"(a) : "l"(p));
    return a;
}
__device__ __forceinline__ void cp16(uint32_t dst, const void* src) {
    asm volatile("cp.async.cg.shared.global [%0], [%1], 16;" :: "r"(dst), "l"(src) : "memory");
}
__device__ __forceinline__ void mma_bf16(float& c0, float& c1, float& c2, float& c3,
                                         uint32_t a0, uint32_t a1, uint32_t a2, uint32_t a3,
                                         uint32_t b0, uint32_t b1) {
    asm volatile(
        "mma.sync.aligned.m16n8k16.row.col.f32.bf16.bf16.f32 "
        "{%0,%1,%2,%3}, {%4,%5,%6,%7}, {%8,%9}, {%0,%1,%2,%3};"
        : "+f"(c0), "+f"(c1), "+f"(c2), "+f"(c3)
        : "r"(a0), "r"(a1), "r"(a2), "r"(a3), "r"(b0), "r"(b1));
}
__device__ __forceinline__ void mma_tf32(float& c0, float& c1, float& c2, float& c3,
                                         uint32_t a0, uint32_t a1, uint32_t a2, uint32_t a3,
                                         uint32_t b0, uint32_t b1) {
    asm volatile(
        "mma.sync.aligned.m16n8k8.row.col.f32.tf32.tf32.f32 "
        "{%0,%1,%2,%3}, {%4,%5,%6,%7}, {%8,%9}, {%0,%1,%2,%3};"
        : "+f"(c0), "+f"(c1), "+f"(c2), "+f"(c3)
        : "r"(a0), "r"(a1), "r"(a2), "r"(a3), "r"(b0), "r"(b1));
}

// ---------------------------------------------------------------------------
// Prep: pack W1 (bf16, k-tile pairs) and W2 (tf32, k-tile pairs).
// ---------------------------------------------------------------------------
__global__ void prep_kernel(const float* __restrict__ W1w, const float* __restrict__ W2w)
{
    int idx = blockIdx.x * blockDim.x + threadIdx.x;
    if (idx < NT * KP4 * 32) {
        int lane = idx & 31, p = (idx >> 5) % KP4, n = idx / (32 * KP4);
        int g = lane >> 2, t = lane & 3;
        int j = n * 8 + g;
        auto w1 = [&](int k) -> float {
            return (j < D && k < D + 1) ? W1w[k * D + j] : 0.f;
        };
        int kk0 = 2 * p, kk1 = 2 * p + 1;
        int a0 = kk0 * 16 + 2 * t, a1 = kk1 * 16 + 2 * t;
        uint4 o;
        o.x = pack_bf16(w1(a0),     w1(a0 + 1));
        o.y = pack_bf16(w1(a0 + 8), w1(a0 + 9));
        o.z = (kk1 < KTB) ? pack_bf16(w1(a1),     w1(a1 + 1)) : 0u;
        o.w = (kk1 < KTB) ? pack_bf16(w1(a1 + 8), w1(a1 + 9)) : 0u;
        g_W1f4[idx] = o;
    } else if (idx < NT * KP4 * 32 + NT * KP2 * 32) {
        int i2 = idx - NT * KP4 * 32;
        int lane = i2 & 31, p = (i2 >> 5) % KP2, n = i2 / (32 * KP2);
        int g = lane >> 2, t = lane & 3;
        int j = n * 8 + g;
        auto w2 = [&](int k) -> uint32_t {
            float v = (j < D && k < 2 * D) ? W2w[k * D + j] : 0.f;
            return f2tf32(v);
        };
        int kk0 = 2 * p, kk1 = 2 * p + 1;
        uint4 o;
        o.x = w2(kk0 * 8 + t);
        o.y = w2(kk0 * 8 + t + 4);
        o.z = (kk1 < KT2) ? w2(kk1 * 8 + t)     : 0u;
        o.w = (kk1 < KT2) ? w2(kk1 * 8 + t + 4) : 0u;
        g_W2f4[i2] = o;
    }
}

__global__ void dummy_kernel() {}

// n-group GEMM: pre-packed A frags; B via uint4 (2 k-tiles per load).
template<int N0, int NB>
__device__ __forceinline__ void gemm_group(const uint32_t af[KTB][4],
                                           const float* bsh, const float* q1s,
                                           int lane, int ja, int jb,
                                           float& p0, float& p1)
{
    float acc[NB][4];
    #pragma unroll
    for (int n = 0; n < NB; ++n) {
        float ba = bsh[(N0 + n) * 8 + ja], bb = bsh[(N0 + n) * 8 + jb];
        acc[n][0] = ba; acc[n][1] = bb; acc[n][2] = ba; acc[n][3] = bb;
    }
    #pragma unroll
    for (int p = 0; p < KP4; ++p) {
        const int k0 = 2 * p, k1 = 2 * p + 1;
        #pragma unroll
        for (int n = 0; n < NB; ++n) {
            uint4 b = __ldg(&g_W1f4[((N0 + n) * KP4 + p) * 32 + lane]);
            mma_bf16(acc[n][0], acc[n][1], acc[n][2], acc[n][3],
                     af[k0][0], af[k0][1], af[k0][2], af[k0][3], b.x, b.y);
            if (k1 < KTB)
                mma_bf16(acc[n][0], acc[n][1], acc[n][2], acc[n][3],
                         af[k1][0], af[k1][1], af[k1][2], af[k1][3], b.z, b.w);
        }
    }
    #pragma unroll
    for (int n = 0; n < NB; ++n) {
        float qa = q1s[(N0 + n) * 8 + ja], qb = q1s[(N0 + n) * 8 + jb];
        p0 += qa * tanh_fast(acc[n][0]) + qb * tanh_fast(acc[n][1]);
        p1 += qa * tanh_fast(acc[n][2]) + qb * tanh_fast(acc[n][3]);
    }
}

// ---------------------------------------------------------------------------
// Kernel A: 4 nodes/block, bf16 MMA, per-warp cp.async gather, 4 blocks/SM.
// ---------------------------------------------------------------------------
__global__ void __launch_bounds__(TA, 4)
attn_kernel(const int* __restrict__ nei, const float* __restrict__ wei,
            const float* __restrict__ s_vec, const float* __restrict__ emb,
            const float* __restrict__ W1b, const float* __restrict__ q1w, int Ntot)
{
    extern __shared__ float sm[];
    float* A    = sm;                    // [M][AW] + 8 pad
    float* q1s  = A + M * AW + 8;        // [104]
    float* bsh  = q1s + 104;             // [104]
    float* ssx  = bsh + 104;             // [NBA][SSW]
    float* score= ssx + NBA * SSW;       // [M]
    int*   nbid = (int*)(score + M);     // [M]

    const int tid  = threadIdx.x;
    const int wid  = tid >> 5;
    const int lane = tid & 31;
    const int g    = lane >> 2;
    const int t    = lane & 3;
    const int node0 = blockIdx.x * NBA;
    if (node0 >= Ntot) return;

    if (tid < M) {
        int r = tid, node = r >> 5, k = r & 31;
        int nn = node0 + node; if (nn >= Ntot) nn = Ntot - 1;
        nbid[r] = nei[nn * Kn + k];
        float* ar = &A[r * AW];
        ar[100] = wei[nn * Kn + k];
        ar[101] = 0.f; ar[102] = 0.f; ar[103] = 0.f;
    }
    if (tid < 8) A[M * AW + tid] = 0.f;
    if (tid < 104) {
        q1s[tid] = (tid < D) ? q1w[tid] : 0.f;
        bsh[tid] = (tid < D) ? W1b[tid] : 0.f;
    }
    for (int i = tid; i < NBA * SSW; i += TA) {
        int node = i / SSW, d = i - node * SSW;
        int nn = node0 + node; if (nn >= Ntot) nn = Ntot - 1;
        ssx[i] = (d < D) ? s_vec[nn * D + d] : (d == D ? 1.f : 0.f);
    }
    __syncthreads();

    const int r0 = wid * 16;
    const int R0 = r0 + g, R1 = R0 + 8;

    // ---- per-warp gather of own 16 rows ----
    {
        const uint32_t abase = smem_u32(A);
        for (int i = lane; i < 16 * 25; i += 32) {
            int rr = i / 25, c = i - rr * 25;
            int r = r0 + rr;
            cp16(abase + (uint32_t)(r * AW + c * 4) * 4u,
                 (const float4*)(emb + (size_t)nbid[r] * D) + c);
        }
        asm volatile("cp.async.commit_group;" ::: "memory");
        asm volatile("cp.async.wait_group 0;" ::: "memory");
        __syncwarp();
    }

    // ---- pack A fragments once, 3 n-groups ----
    {
        const float* srow = &ssx[(wid >> 1) * SSW];
        uint32_t af[KTB][4];
        #pragma unroll
        for (int kk = 0; kk < KTB; ++kk) {
            const int c0 = kk * 16 + 2 * t;
            float2 h0 = *(const float2*)&A[R0 * AW + c0];
            float2 h1 = *(const float2*)&A[R1 * AW + c0];
            float2 h2 = *(const float2*)&A[R0 * AW + c0 + 8];
            float2 h3 = *(const float2*)&A[R1 * AW + c0 + 8];
            float2 s0 = *(const float2*)&srow[c0];
            float2 s1 = *(const float2*)&srow[c0 + 8];
            af[kk][0] = pack_bf16(h0.x * s0.x, h0.y * s0.y);
            af[kk][1] = pack_bf16(h1.x * s0.x, h1.y * s0.y);
            af[kk][2] = pack_bf16(h2.x * s1.x, h2.y * s1.y);
            af[kk][3] = pack_bf16(h3.x * s1.x, h3.y * s1.y);
        }
        const int ja = 2 * t, jb = ja + 1;
        float p0 = 0.f, p1 = 0.f;
        gemm_group<0, 5>(af, bsh, q1s, lane, ja, jb, p0, p1);
        gemm_group<5, 4>(af, bsh, q1s, lane, ja, jb, p0, p1);
        gemm_group<9, 4>(af, bsh, q1s, lane, ja, jb, p0, p1);
        p0 += __shfl_xor_sync(~0u, p0, 1); p0 += __shfl_xor_sync(~0u, p0, 2);
        p1 += __shfl_xor_sync(~0u, p1, 1); p1 += __shfl_xor_sync(~0u, p1, 2);
        if (t == 0) { score[R0] = p0; score[R1] = p1; }
    }
    __syncthreads();

    if (wid < 4) {
        float sc = score[wid * 32 + lane];
        float mx = sc;
        #pragma unroll
        for (int o = 16; o > 0; o >>= 1) mx = fmaxf(mx, __shfl_xor_sync(~0u, mx, o));
        float e = __expf(sc - mx);
        float sum = e;
        #pragma unroll
        for (int o = 16; o > 0; o >>= 1) sum += __shfl_xor_sync(~0u, sum, o);
        score[wid * 32 + lane] = e / sum;
    }
    __syncthreads();

    // ---- msg on all 8 warps ----
    {
        const int node = wid >> 1;
        if (node0 + node < Ntot) {
            const float* at = &score[node * 32];
            const int dbase = (wid & 1) * 64;
            #pragma unroll
            for (int c = 0; c < 2; ++c) {
                int d = dbase + c * 32 + lane;
                if (d < D) {
                    float acc = 0.f;
                    const float* ap = &A[(node * 32) * AW + d];
                    #pragma unroll
                    for (int k = 0; k < Kn; ++k) acc += at[k] * ap[k * AW];
                    g_msg[(size_t)(node0 + node) * D + d] = acc;
                }
            }
        }
    }
}

// ---------------------------------------------------------------------------
// Kernel B (tf32 MMA): W2 uint4 frags from L2, KT2=25 exact, 4 blocks/SM.
// ---------------------------------------------------------------------------
__global__ void __launch_bounds__(256, 4)
mlp_kernel(const int* __restrict__ nodes, const float* __restrict__ emb,
           const float* __restrict__ W2b, float* __restrict__ out, int Ntot)
{
    extern __shared__ float sm[];
    float* A   = sm;                       // [MN][SA2]
    float* b2s = A + MN * SA2;             // [104]
    int*   nid = (int*)(b2s + 104);        // [MN]

    const int tid  = threadIdx.x;
    const int wid  = tid >> 5;
    const int lane = tid & 31;
    const int g    = lane >> 2;
    const int t    = lane & 3;
    const int node0 = blockIdx.x * MN;
    if (node0 >= Ntot) return;

    if (tid < 104) b2s[tid] = (tid < D) ? W2b[tid] : 0.f;
    if (tid < MN) {
        int nn = node0 + tid; if (nn >= Ntot) nn = Ntot - 1;
        nid[tid] = nodes[nn];
    }
    __syncthreads();

    for (int r = wid; r < MN; r += 8) {
        int mrow = node0 + r; if (mrow >= Ntot) mrow = Ntot - 1;
        float* ar = &A[r * SA2];
        if (lane < 25) {
            ((float4*)ar)[lane] = ((const float4*)&emb[(size_t)nid[r] * D])[lane];
            ((float4*)(ar + 100))[lane] = ((const float4*)&g_msg[(size_t)mrow * D])[lane];
        }
    }
    __syncthreads();

    const int wg  = wid >> 2;
    const int r0  = (wid & 3) * 16;
    const int R0  = r0 + g, R1 = R0 + 8;
    const int nt0 = wg ? 7 : 0;
    const int ntn = wg ? 6 : 7;
    const int ja  = 2 * t, jb = ja + 1;

    #pragma unroll
    for (int layer = 0; layer < 2; ++layer) {
        float acc[7][4];
        for (int n = 0; n < ntn; ++n) {
            float ba = b2s[(nt0 + n) * 8 + ja], bb = b2s[(nt0 + n) * 8 + jb];
            acc[n][0] = ba; acc[n][1] = bb; acc[n][2] = ba; acc[n][3] = bb;
        }
        #pragma unroll
        for (int p = 0; p < KP2; ++p) {
            const int kk0 = 2 * p, kk1 = 2 * p + 1;
            const int c0 = kk0 * 8 + t;
            uint32_t a0 = f2tf32(A[R0 * SA2 + c0]);
            uint32_t a1 = f2tf32(A[R1 * SA2 + c0]);
            uint32_t a2 = f2tf32(A[R0 * SA2 + c0 + 4]);
            uint32_t a3 = f2tf32(A[R1 * SA2 + c0 + 4]);
            uint32_t a4 = 0, a5 = 0, a6 = 0, a7 = 0;
            if (kk1 < KT2) {
                const int c1 = kk1 * 8 + t;
                a4 = f2tf32(A[R0 * SA2 + c1]);
                a5 = f2tf32(A[R1 * SA2 + c1]);
                a6 = f2tf32(A[R0 * SA2 + c1 + 4]);
                a7 = f2tf32(A[R1 * SA2 + c1 + 4]);
            }
            for (int n = 0; n < ntn; ++n) {
                uint4 b = __ldg(&g_W2f4[((nt0 + n) * KP2 + p) * 32 + lane]);
                mma_tf32(acc[n][0], acc[n][1], acc[n][2], acc[n][3],
                         a0, a1, a2, a3, b.x, b.y);
                if (kk1 < KT2)
                    mma_tf32(acc[n][0], acc[n][1], acc[n][2], acc[n][3],
                             a4, a5, a6, a7, b.z, b.w);
            }
        }
        __syncthreads();
        if (layer == 0) {
            for (int n = 0; n < ntn; ++n) {
                int j0 = (nt0 + n) * 8 + ja, j1 = j0 + 1;
                if (j0 < D) { A[R0 * SA2 + j0] = fmaxf(acc[n][0], 0.f);
                              A[R1 * SA2 + j0] = fmaxf(acc[n][2], 0.f); }
                if (j1 < D) { A[R0 * SA2 + j1] = fmaxf(acc[n][1], 0.f);
                              A[R1 * SA2 + j1] = fmaxf(acc[n][3], 0.f); }
            }
            __syncthreads();
        } else {
            int n0 = node0 + R0, n1 = node0 + R1;
            for (int n = 0; n < ntn; ++n) {
                int j0 = (nt0 + n) * 8 + ja, j1 = j0 + 1;
                if (n0 < Ntot) {
                    if (j0 < D) out[(size_t)n0 * D + j0] = fmaxf(acc[n][0], 0.f);
                    if (j1 < D) out[(size_t)n0 * D + j1] = fmaxf(acc[n][1], 0.f);
                }
                if (n1 < Ntot) {
                    if (j0 < D) out[(size_t)n1 * D + j0] = fmaxf(acc[n][2], 0.f);
                    if (j1 < D) out[(size_t)n1 * D + j1] = fmaxf(acc[n][3], 0.f);
                }
            }
        }
    }
}

// ---------------------------------------------------------------------------
extern "C" void kernel_launch(void* const* d_in, const int* in_sizes, int n_in,
                              void* d_out, int out_size)
{
    const int*   nodes = (const int*)  d_in[0];
    const int*   nei   = (const int*)  d_in[1];
    const float* wei   = (const float*)d_in[2];
    const float* s_vec = (const float*)d_in[3];
    const float* emb   = (const float*)d_in[4];
    const float* W1w   = (const float*)d_in[5];
    const float* W1b   = (const float*)d_in[6];
    const float* q1w   = (const float*)d_in[7];
    const float* W2w   = (const float*)d_in[8];
    const float* W2b   = (const float*)d_in[9];
    float* out = (float*)d_out;

    const int N = in_sizes[0];

    const int smemA = (M * AW + 8 + 104 + 104 + NBA * SSW + M + M) * 4;
    const int smemB = (MN * SA2 + 104) * 4 + MN * 4;

    cudaFuncSetAttribute(attn_kernel, cudaFuncAttributeMaxDynamicSharedMemorySize, smemA);
    cudaFuncSetAttribute(mlp_kernel,  cudaFuncAttributeMaxDynamicSharedMemorySize, smemB);

    const int prepN = NT * KP4 * 32 + NT * KP2 * 32;
    prep_kernel<<<(prepN + 255) / 256, 256>>>(W1w, W2w);
    dummy_kernel<<<1, 32>>>();   // pad so ncu's profiled launch (#4) = full attn
    dummy_kernel<<<1, 32>>>();
    attn_kernel<<<(N + NBA - 1) / NBA, TA, smemA>>>(nei, wei, s_vec, emb, W1b, q1w, N);
    mlp_kernel<<<(N + MN - 1) / MN, 256, smemB>>>(nodes, emb, W2b, out, N);
}

// round 12
// speedup vs baseline: 1.1033x; 1.1033x over previous
#include <cuda_runtime.h>
#include <cstdint>

#define D    100
#define Kn   32
#define NBA  2            // attn nodes per block -> M = 64
#define M    64
#define AW   104          // A row stride (raw h; cols 100..103 = wei,0,0,0)
#define TA   128
#define NMAX 50000
#define NT   13
#define KTB  7            // attn k tiles of 16 (112, zero-padded from 101)
#define SSW  112
// mlp
#define MN   64
#define SA2  212
#define KT2  25           // 2D = 200 = exactly 25 k-tiles of 8 (no padding)

__device__ float g_msg[NMAX * D];
__device__ uint2  g_W1f[NT * KTB * 32];
__device__ float2 g_W2f[NT * KT2 * 32];

__device__ __forceinline__ float tanh_fast(float x) {
    float r; asm("tanh.approx.f32 %0, %1;" : "=f"(r) : "f"(x)); return r;
}
__device__ __forceinline__ uint32_t f2tf32(float x) {
    uint32_t r; asm("cvt.rna.tf32.f32 %0, %1;" : "=r"(r) : "f"(x)); return r;
}
__device__ __forceinline__ uint32_t pack_bf16(float lo, float hi) {
    uint32_t r; asm("cvt.rn.bf16x2.f32 %0, %1, %2;" : "=r"(r) : "f"(hi), "f"(lo)); return r;
}
__device__ __forceinline__ uint32_t smem_u32(const void* p) {
    uint32_t a;
    asm("{ .reg .u64 t; cvta.to.shared.u64 t, %1; cvt.u32.u64 %0, t; }" : "=r"(a) : "l"(p));
    return a;
}
__device__ __forceinline__ void cp16(uint32_t dst, const void* src) {
    asm volatile("cp.async.cg.shared.global [%0], [%1], 16;" :: "r"(dst), "l"(src) : "memory");
}
__device__ __forceinline__ void mma_bf16(float& c0, float& c1, float& c2, float& c3,
                                         uint32_t a0, uint32_t a1, uint32_t a2, uint32_t a3,
                                         uint32_t b0, uint32_t b1) {
    asm volatile(
        "mma.sync.aligned.m16n8k16.row.col.f32.bf16.bf16.f32 "
        "{%0,%1,%2,%3}, {%4,%5,%6,%7}, {%8,%9}, {%0,%1,%2,%3};"
        : "+f"(c0), "+f"(c1), "+f"(c2), "+f"(c3)
        : "r"(a0), "r"(a1), "r"(a2), "r"(a3), "r"(b0), "r"(b1));
}
__device__ __forceinline__ void mma_tf32(float& c0, float& c1, float& c2, float& c3,
                                         uint32_t a0, uint32_t a1, uint32_t a2, uint32_t a3,
                                         uint32_t b0, uint32_t b1) {
    asm volatile(
        "mma.sync.aligned.m16n8k8.row.col.f32.tf32.tf32.f32 "
        "{%0,%1,%2,%3}, {%4,%5,%6,%7}, {%8,%9}, {%0,%1,%2,%3};"
        : "+f"(c0), "+f"(c1), "+f"(c2), "+f"(c3)
        : "r"(a0), "r"(a1), "r"(a2), "r"(a3), "r"(b0), "r"(b1));
}

// ---------------------------------------------------------------------------
// Prep: pack W1 (bf16 m16n8k16 frags) and W2 (tf32 m16n8k8 frags, 25 tiles).
// ---------------------------------------------------------------------------
__global__ void prep_kernel(const float* __restrict__ W1w, const float* __restrict__ W2w)
{
    int idx = blockIdx.x * blockDim.x + threadIdx.x;
    if (idx < NT * KTB * 32) {
        int lane = idx & 31, kk = (idx >> 5) % KTB, n = idx / (32 * KTB);
        int g = lane >> 2, t = lane & 3;
        int j = n * 8 + g;
        auto w1 = [&](int k) -> float {
            return (j < D && k < D + 1) ? W1w[k * D + j] : 0.f;
        };
        int k0 = kk * 16 + 2 * t;
        uint2 o;
        o.x = pack_bf16(w1(k0),     w1(k0 + 1));
        o.y = pack_bf16(w1(k0 + 8), w1(k0 + 9));
        g_W1f[idx] = o;
    } else if (idx < NT * KTB * 32 + NT * KT2 * 32) {
        int i2 = idx - NT * KTB * 32;
        int lane = i2 & 31, kk = (i2 >> 5) % KT2, n = i2 / (32 * KT2);
        int g = lane >> 2, t = lane & 3;
        int j = n * 8 + g;
        int k0 = kk * 8 + t, k1 = k0 + 4;
        float v0 = (j < D) ? W2w[k0 * D + j] : 0.f;      // k0,k1 < 200 always
        float v1 = (j < D) ? W2w[k1 * D + j] : 0.f;
        float2 o;
        o.x = __uint_as_float(f2tf32(v0));
        o.y = __uint_as_float(f2tf32(v1));
        g_W2f[i2] = o;
    }
}

__global__ void dummy_kernel() {}

// n-group GEMM piece: pre-packed A frags; B via LDG.64 from L2.
template<int N0, int NB>
__device__ __forceinline__ void gemm_group(const uint32_t af[KTB][4],
                                           const float* bsh, const float* q1s,
                                           int lane, int ja, int jb,
                                           float& p0, float& p1)
{
    float acc[NB][4];
    #pragma unroll
    for (int n = 0; n < NB; ++n) {
        float ba = bsh[(N0 + n) * 8 + ja], bb = bsh[(N0 + n) * 8 + jb];
        acc[n][0] = ba; acc[n][1] = bb; acc[n][2] = ba; acc[n][3] = bb;
    }
    #pragma unroll
    for (int kk = 0; kk < KTB; ++kk) {
        #pragma unroll
        for (int n = 0; n < NB; ++n) {
            uint2 b = __ldg(&g_W1f[((N0 + n) * KTB + kk) * 32 + lane]);
            mma_bf16(acc[n][0], acc[n][1], acc[n][2], acc[n][3],
                     af[kk][0], af[kk][1], af[kk][2], af[kk][3], b.x, b.y);
        }
    }
    #pragma unroll
    for (int n = 0; n < NB; ++n) {
        float qa = q1s[(N0 + n) * 8 + ja], qb = q1s[(N0 + n) * 8 + jb];
        p0 += qa * tanh_fast(acc[n][0]) + qb * tanh_fast(acc[n][1]);
        p1 += qa * tanh_fast(acc[n][2]) + qb * tanh_fast(acc[n][3]);
    }
}

// ---------------------------------------------------------------------------
// Kernel A: 2 nodes/block (M=64), 128 threads, 8 blocks/SM.
// ---------------------------------------------------------------------------
__global__ void __launch_bounds__(TA, 8)
attn_kernel(const int* __restrict__ nei, const float* __restrict__ wei,
            const float* __restrict__ s_vec, const float* __restrict__ emb,
            const float* __restrict__ W1b, const float* __restrict__ q1w, int Ntot)
{
    extern __shared__ float sm[];
    float* A    = sm;                    // [M][AW] + 8 pad
    float* q1s  = A + M * AW + 8;        // [104]
    float* bsh  = q1s + 104;             // [104]
    float* ssx  = bsh + 104;             // [NBA][SSW]
    float* score= ssx + NBA * SSW;       // [M]
    int*   nbid = (int*)(score + M);     // [M]

    const int tid  = threadIdx.x;
    const int wid  = tid >> 5;           // 0..3
    const int lane = tid & 31;
    const int g    = lane >> 2;
    const int t    = lane & 3;
    const int node0 = blockIdx.x * NBA;
    if (node0 >= Ntot) return;

    if (tid < M) {
        int r = tid, node = r >> 5, k = r & 31;
        int nn = node0 + node; if (nn >= Ntot) nn = Ntot - 1;
        nbid[r] = nei[nn * Kn + k];
        float* ar = &A[r * AW];
        ar[100] = wei[nn * Kn + k];
        ar[101] = 0.f; ar[102] = 0.f; ar[103] = 0.f;
    }
    if (tid < 8) A[M * AW + tid] = 0.f;
    if (tid < 104) {
        q1s[tid] = (tid < D) ? q1w[tid] : 0.f;
        bsh[tid] = (tid < D) ? W1b[tid] : 0.f;
    }
    for (int i = tid; i < NBA * SSW; i += TA) {
        int node = i / SSW, d = i - node * SSW;
        int nn = node0 + node; if (nn >= Ntot) nn = Ntot - 1;
        ssx[i] = (d < D) ? s_vec[nn * D + d] : (d == D ? 1.f : 0.f);
    }
    __syncthreads();

    const int r0 = wid * 16;
    const int R0 = r0 + g, R1 = R0 + 8;

    // ---- per-warp gather of own 16 rows (25 x 16B each) ----
    {
        const uint32_t abase = smem_u32(A);
        for (int i = lane; i < 16 * 25; i += 32) {
            int rr = i / 25, c = i - rr * 25;
            int r = r0 + rr;
            cp16(abase + (uint32_t)(r * AW + c * 4) * 4u,
                 (const float4*)(emb + (size_t)nbid[r] * D) + c);
        }
        asm volatile("cp.async.commit_group;" ::: "memory");
        asm volatile("cp.async.wait_group 0;" ::: "memory");
        __syncwarp();
    }

    // ---- pack A fragments once, 3 n-groups ----
    {
        const float* srow = &ssx[(wid >> 1) * SSW];
        uint32_t af[KTB][4];
        #pragma unroll
        for (int kk = 0; kk < KTB; ++kk) {
            const int c0 = kk * 16 + 2 * t;
            float2 h0 = *(const float2*)&A[R0 * AW + c0];
            float2 h1 = *(const float2*)&A[R1 * AW + c0];
            float2 h2 = *(const float2*)&A[R0 * AW + c0 + 8];
            float2 h3 = *(const float2*)&A[R1 * AW + c0 + 8];
            float2 s0 = *(const float2*)&srow[c0];
            float2 s1 = *(const float2*)&srow[c0 + 8];
            af[kk][0] = pack_bf16(h0.x * s0.x, h0.y * s0.y);
            af[kk][1] = pack_bf16(h1.x * s0.x, h1.y * s0.y);
            af[kk][2] = pack_bf16(h2.x * s1.x, h2.y * s1.y);
            af[kk][3] = pack_bf16(h3.x * s1.x, h3.y * s1.y);
        }
        const int ja = 2 * t, jb = ja + 1;
        float p0 = 0.f, p1 = 0.f;
        gemm_group<0, 5>(af, bsh, q1s, lane, ja, jb, p0, p1);
        gemm_group<5, 4>(af, bsh, q1s, lane, ja, jb, p0, p1);
        gemm_group<9, 4>(af, bsh, q1s, lane, ja, jb, p0, p1);
        p0 += __shfl_xor_sync(~0u, p0, 1); p0 += __shfl_xor_sync(~0u, p0, 2);
        p1 += __shfl_xor_sync(~0u, p1, 1); p1 += __shfl_xor_sync(~0u, p1, 2);
        if (t == 0) { score[R0] = p0; score[R1] = p1; }
    }
    __syncthreads();

    // ---- softmax (warps 0..1, warp = node) ----
    if (wid < NBA) {
        float sc = score[wid * 32 + lane];
        float mx = sc;
        #pragma unroll
        for (int o = 16; o > 0; o >>= 1) mx = fmaxf(mx, __shfl_xor_sync(~0u, mx, o));
        float e = __expf(sc - mx);
        float sum = e;
        #pragma unroll
        for (int o = 16; o > 0; o >>= 1) sum += __shfl_xor_sync(~0u, sum, o);
        score[wid * 32 + lane] = e / sum;
    }
    __syncthreads();

    // ---- msg on all 4 warps: warp = (node = wid>>1, d-half = wid&1) ----
    {
        const int node = wid >> 1;
        if (node0 + node < Ntot) {
            const float* at = &score[node * 32];
            const int dbase = (wid & 1) * 64;
            #pragma unroll
            for (int c = 0; c < 2; ++c) {
                int d = dbase + c * 32 + lane;
                if (d < D) {
                    float acc = 0.f;
                    const float* ap = &A[(node * 32) * AW + d];
                    #pragma unroll
                    for (int k = 0; k < Kn; ++k) acc += at[k] * ap[k * AW];
                    g_msg[(size_t)(node0 + node) * D + d] = acc;
                }
            }
        }
    }
}

// ---------------------------------------------------------------------------
// Kernel B (tf32 MMA): R10 version, KT2=25 exact, 3 blocks/SM.
// ---------------------------------------------------------------------------
__global__ void __launch_bounds__(256, 3)
mlp_kernel(const int* __restrict__ nodes, const float* __restrict__ emb,
           const float* __restrict__ W2b, float* __restrict__ out, int Ntot)
{
    extern __shared__ float sm[];
    float* A   = sm;                       // [MN][SA2]
    float* b2s = A + MN * SA2;             // [104]
    int*   nid = (int*)(b2s + 104);        // [MN]

    const int tid  = threadIdx.x;
    const int wid  = tid >> 5;
    const int lane = tid & 31;
    const int g    = lane >> 2;
    const int t    = lane & 3;
    const int node0 = blockIdx.x * MN;
    if (node0 >= Ntot) return;

    if (tid < 104) b2s[tid] = (tid < D) ? W2b[tid] : 0.f;
    if (tid < MN) {
        int nn = node0 + tid; if (nn >= Ntot) nn = Ntot - 1;
        nid[tid] = nodes[nn];
    }
    __syncthreads();

    for (int r = wid; r < MN; r += 8) {
        int mrow = node0 + r; if (mrow >= Ntot) mrow = Ntot - 1;
        float* ar = &A[r * SA2];
        if (lane < 25) {
            ((float4*)ar)[lane] = ((const float4*)&emb[(size_t)nid[r] * D])[lane];
            ((float4*)(ar + 100))[lane] = ((const float4*)&g_msg[(size_t)mrow * D])[lane];
        }
    }
    __syncthreads();

    const int wg  = wid >> 2;
    const int r0  = (wid & 3) * 16;
    const int R0  = r0 + g, R1 = R0 + 8;
    const int nt0 = wg ? 7 : 0;
    const int ntn = wg ? 6 : 7;
    const int ja  = 2 * t, jb = ja + 1;

    #pragma unroll
    for (int layer = 0; layer < 2; ++layer) {
        float acc[7][4];
        for (int n = 0; n < ntn; ++n) {
            float ba = b2s[(nt0 + n) * 8 + ja], bb = b2s[(nt0 + n) * 8 + jb];
            acc[n][0] = ba; acc[n][1] = bb; acc[n][2] = ba; acc[n][3] = bb;
        }
        #pragma unroll
        for (int kk = 0; kk < KT2; ++kk) {
            const int c0 = kk * 8 + t;
            uint32_t a0 = f2tf32(A[R0 * SA2 + c0]);
            uint32_t a1 = f2tf32(A[R1 * SA2 + c0]);
            uint32_t a2 = f2tf32(A[R0 * SA2 + c0 + 4]);
            uint32_t a3 = f2tf32(A[R1 * SA2 + c0 + 4]);
            for (int n = 0; n < ntn; ++n) {
                float2 b = __ldg(&g_W2f[((nt0 + n) * KT2 + kk) * 32 + lane]);
                mma_tf32(acc[n][0], acc[n][1], acc[n][2], acc[n][3],
                         a0, a1, a2, a3,
                         __float_as_uint(b.x), __float_as_uint(b.y));
            }
        }
        __syncthreads();
        if (layer == 0) {
            for (int n = 0; n < ntn; ++n) {
                int j0 = (nt0 + n) * 8 + ja, j1 = j0 + 1;
                if (j0 < D) { A[R0 * SA2 + j0] = fmaxf(acc[n][0], 0.f);
                              A[R1 * SA2 + j0] = fmaxf(acc[n][2], 0.f); }
                if (j1 < D) { A[R0 * SA2 + j1] = fmaxf(acc[n][1], 0.f);
                              A[R1 * SA2 + j1] = fmaxf(acc[n][3], 0.f); }
            }
            __syncthreads();
        } else {
            int n0 = node0 + R0, n1 = node0 + R1;
            for (int n = 0; n < ntn; ++n) {
                int j0 = (nt0 + n) * 8 + ja, j1 = j0 + 1;
                if (n0 < Ntot) {
                    if (j0 < D) out[(size_t)n0 * D + j0] = fmaxf(acc[n][0], 0.f);
                    if (j1 < D) out[(size_t)n0 * D + j1] = fmaxf(acc[n][1], 0.f);
                }
                if (n1 < Ntot) {
                    if (j0 < D) out[(size_t)n1 * D + j0] = fmaxf(acc[n][2], 0.f);
                    if (j1 < D) out[(size_t)n1 * D + j1] = fmaxf(acc[n][3], 0.f);
                }
            }
        }
    }
}

// ---------------------------------------------------------------------------
extern "C" void kernel_launch(void* const* d_in, const int* in_sizes, int n_in,
                              void* d_out, int out_size)
{
    const int*   nodes = (const int*)  d_in[0];
    const int*   nei   = (const int*)  d_in[1];
    const float* wei   = (const float*)d_in[2];
    const float* s_vec = (const float*)d_in[3];
    const float* emb   = (const float*)d_in[4];
    const float* W1w   = (const float*)d_in[5];
    const float* W1b   = (const float*)d_in[6];
    const float* q1w   = (const float*)d_in[7];
    const float* W2w   = (const float*)d_in[8];
    const float* W2b   = (const float*)d_in[9];
    float* out = (float*)d_out;

    const int N = in_sizes[0];

    const int smemA = (M * AW + 8 + 104 + 104 + NBA * SSW + M + M) * 4;
    const int smemB = (MN * SA2 + 104) * 4 + MN * 4;

    cudaFuncSetAttribute(attn_kernel, cudaFuncAttributeMaxDynamicSharedMemorySize, smemA);
    cudaFuncSetAttribute(mlp_kernel,  cudaFuncAttributeMaxDynamicSharedMemorySize, smemB);

    const int prepN = NT * KTB * 32 + NT * KT2 * 32;
    prep_kernel<<<(prepN + 255) / 256, 256>>>(W1w, W2w);
    dummy_kernel<<<1, 32>>>();   // pad so ncu's profiled launch (#4) = full attn
    dummy_kernel<<<1, 32>>>();
    attn_kernel<<<(N + NBA - 1) / NBA, TA, smemA>>>(nei, wei, s_vec, emb, W1b, q1w, N);
    mlp_kernel<<<(N + MN - 1) / MN, 256, smemB>>>(nodes, emb, W2b, out, N);
}